// round 16
// baseline (speedup 1.0000x reference)
#include <cuda_runtime.h>
#include <math.h>

#define NITEMS   32768
#define DIM      512
#define KSEL     16
#define LAMBDA   0.5f
#define DECAYF   0.85f
#define NTHREADS 512
#define WPB      16                     // warps per block
#define RPW      14                     // rows per warp (in registers)
#define RPB      (WPB * RPW)            // 224 rows per block; 148*224 = 33152 >= 32768
#define MAXB     512
#define NGW      (MAXB * WPB)

// ---------------- device scratch (no allocations allowed) ----------------
__device__ __align__(16) uint4  g_wcand[2][NGW][32];   // per-warp speculative candidate rows (int8)
__device__ __align__(8)  float2 g_winfo[2][NGW];       // (rel, inv_scale) of warp candidate
__device__ float                g_m_part[MAXB];        // online-softmax partial max
__device__ float                g_s_part[MAXB];        // online-softmax partial sum
// winner-round slots: best and cnt on SEPARATE 128B lines (poll/publish decoupled)
__device__ __align__(128) unsigned long long g_best_a[KSEL][16];
__device__ __align__(128) unsigned           g_cnt_a[KSEL][32];
__device__ unsigned int         g_bar;                 // monotonic barrier (replay-safe reset guard)

// order-preserving float->u32 (monotone increasing); 0 reserved for "invalid"
__device__ __forceinline__ unsigned flip_f(float s) {
    unsigned b = __float_as_uint(s);
    return (b & 0x80000000u) ? ~b : (b | 0x80000000u);
}
__device__ __forceinline__ float warp_sum_xor(float v) {
    #pragma unroll
    for (int o = 16; o > 0; o >>= 1) v += __shfl_xor_sync(0xffffffffu, v, o);
    return v;
}
__device__ __forceinline__ void merge_ms(float& m, float& s, float m2, float s2) {
    float M = fmaxf(m, m2);
    s = s * expf(m - M) + s2 * expf(m2 - M);
    m = M;
}
// publish: no-return REDs; .release on the arrive orders cand STGs + max before it
__device__ __forceinline__ void slot_publish(int k, unsigned long long bb, bool have) {
    if (have)
        asm volatile("red.relaxed.gpu.global.max.u64 [%0], %1;"
                     :: "l"(&g_best_a[k][0]), "l"(bb) : "memory");
    asm volatile("red.release.gpu.global.add.u32 [%0], %1;"
                 :: "l"(&g_cnt_a[k][0]), "r"(1u) : "memory");
}
// scalar poll on the cnt line only
__device__ __forceinline__ void cnt_wait(int k, unsigned nb) {
    unsigned c;
    do {
        asm volatile("ld.volatile.global.u32 %0, [%1];" : "=r"(c) : "l"(&g_cnt_a[k][0]));
    } while (c < nb);
}
// pack 4 s32 -> 4 saturated s8 bytes (2 ops; byte order is consistent => dp4a-invariant)
__device__ __forceinline__ unsigned pack4_s8(int q0, int q1, int q2, int q3) {
    unsigned t, r, z = 0u;
    asm("cvt.pack.sat.s8.s32.b32 %0, %1, %2, %3;" : "=r"(t) : "r"(q3), "r"(q2), "r"(z));
    asm("cvt.pack.sat.s8.s32.b32 %0, %1, %2, %3;" : "=r"(r) : "r"(q1), "r"(q0), "r"(t));
    return r;
}

__global__ void __launch_bounds__(NTHREADS, 1)
ranking_kernel(const float* __restrict__ pred,
               const float* __restrict__ E,
               float* __restrict__ out,
               int nb)
{
    __shared__ __align__(16) uint4 sh_v4[32];           // staged winner vector, 512 B
    __shared__ unsigned sh_e[WPB];
    __shared__ int      sh_r[WPB];
    __shared__ int      sh_widx;
    __shared__ float    sh_vinv, sh_bm, sh_bs;
    __shared__ float    sh_m[WPB], sh_s[WPB];

    const int tid   = threadIdx.x;
    const int bid   = blockIdx.x;
    const int lid   = tid & 31;
    const int wid   = tid >> 5;
    const int rbase = bid * RPB + wid * RPW;
    const int gw    = bid * WPB + wid;
    const int gthreads = nb * NTHREADS;
    const int gtid     = bid * NTHREADS + tid;

    // reset slots (graph-replay safe); guarded by g_bar before any slot use
    if (bid == 0 && tid == 0) {
        #pragma unroll
        for (int i = 0; i < KSEL; i++) { g_best_a[i][0] = 0ull; g_cnt_a[i][0] = 0u; }
    }

    // ---------------- A1: online softmax partials over predictions ----------------
    float m = -1e30f, s = 0.f;
    for (int i = gtid; i < NITEMS; i += gthreads) {
        float p = pred[i];
        float M = fmaxf(m, p);
        s = s * expf(m - M) + expf(p - M);
        m = M;
    }
    #pragma unroll
    for (int o = 16; o > 0; o >>= 1) {
        float m2 = __shfl_xor_sync(0xffffffffu, m, o);
        float s2 = __shfl_xor_sync(0xffffffffu, s, o);
        merge_ms(m, s, m2, s2);
    }
    __syncthreads();
    if (lid == 0) { sh_m[wid] = m; sh_s[wid] = s; }
    __syncthreads();
    if (wid == 0) {
        float pm = (lid < WPB) ? sh_m[lid] : -1e30f;
        float ps = (lid < WPB) ? sh_s[lid] : 0.f;
        #pragma unroll
        for (int o = 16; o > 0; o >>= 1) {
            float m2 = __shfl_xor_sync(0xffffffffu, pm, o);
            float s2 = __shfl_xor_sync(0xffffffffu, ps, o);
            merge_ms(pm, ps, m2, s2);
        }
        if (lid == 0) { g_m_part[bid] = pm; g_s_part[bid] = ps; }
    }

    // arrive the replay-guard barrier (covers slot reset + softmax partials)
    unsigned bar_target = 0u;
    if (tid == 0) {
        __threadfence();
        unsigned tk = atomicAdd(&g_bar, 1u) + 1u;
        bar_target = ((tk + (unsigned)nb - 1u) / (unsigned)nb) * (unsigned)nb;
    }

    // ---------------- A2: normalize -> per-row-scaled int8 into REGISTERS ----------------
    uint4 a[RPW];
    const bool  mine  = (lid < RPW) && (rbase + lid < NITEMS);
    const int   myrow = rbase + lid;
    float my_inva = 0.f, mypred = -1e30f;
    if (mine) mypred = pred[myrow];

    {
        const float4* Erow = reinterpret_cast<const float4*>(E) + (size_t)rbase * (DIM / 4);
        float4 cur[4];
        if (rbase < NITEMS) {
            #pragma unroll
            for (int j = 0; j < 4; j++) cur[j] = Erow[j * 32 + lid];
        }
        #pragma unroll
        for (int i = 0; i < RPW; i++) {
            int row = rbase + i;
            float4 nxt[4];
            bool have_n = (i + 1 < RPW) && (row + 1 < NITEMS);
            if (have_n) {
                const float4* Er2 = Erow + (size_t)(i + 1) * (DIM / 4);
                #pragma unroll
                for (int j = 0; j < 4; j++) nxt[j] = Er2[j * 32 + lid];
            }
            if (row < NITEMS) {
                // sum of squares + max|x| over the RAW row (quant scale is norm-invariant)
                float ss2 = 0.f, am = 0.f;
                #pragma unroll
                for (int j = 0; j < 4; j++) {
                    ss2 += cur[j].x * cur[j].x + cur[j].y * cur[j].y
                         + cur[j].z * cur[j].z + cur[j].w * cur[j].w;
                    am = fmaxf(am, fabsf(cur[j].x)); am = fmaxf(am, fabsf(cur[j].y));
                    am = fmaxf(am, fabsf(cur[j].z)); am = fmaxf(am, fabsf(cur[j].w));
                }
                ss2 = warp_sum_xor(ss2);
                unsigned amu = __reduce_max_sync(0xffffffffu, __float_as_uint(am));
                float xmax = __uint_as_float(amu);
                const float inv = 1.0f / (sqrtf(ss2) + 1e-12f);
                const float qs   = 127.0f / xmax;
                const float inva = xmax * inv * (1.0f / 127.0f);
                int q[16];
                q[0]  = __float2int_rn(cur[0].x * qs); q[1]  = __float2int_rn(cur[0].y * qs);
                q[2]  = __float2int_rn(cur[0].z * qs); q[3]  = __float2int_rn(cur[0].w * qs);
                q[4]  = __float2int_rn(cur[1].x * qs); q[5]  = __float2int_rn(cur[1].y * qs);
                q[6]  = __float2int_rn(cur[1].z * qs); q[7]  = __float2int_rn(cur[1].w * qs);
                q[8]  = __float2int_rn(cur[2].x * qs); q[9]  = __float2int_rn(cur[2].y * qs);
                q[10] = __float2int_rn(cur[2].z * qs); q[11] = __float2int_rn(cur[2].w * qs);
                q[12] = __float2int_rn(cur[3].x * qs); q[13] = __float2int_rn(cur[3].y * qs);
                q[14] = __float2int_rn(cur[3].z * qs); q[15] = __float2int_rn(cur[3].w * qs);
                a[i].x = pack4_s8(q[0],  q[1],  q[2],  q[3]);
                a[i].y = pack4_s8(q[4],  q[5],  q[6],  q[7]);
                a[i].z = pack4_s8(q[8],  q[9],  q[10], q[11]);
                a[i].w = pack4_s8(q[12], q[13], q[14], q[15]);
                if (lid == i) my_inva = inva;
            } else {
                a[i] = make_uint4(0u, 0u, 0u, 0u);
            }
            #pragma unroll
            for (int j = 0; j < 4; j++) cur[j] = nxt[j];
        }
    }

    // ---------- t=0: argmax(pred) (== argmax(rel), softmax monotone) ----------
    {
        unsigned e = mine ? flip_f(mypred) : 0u;
        unsigned mx = __reduce_max_sync(0xffffffffu, e);
        unsigned ball = __ballot_sync(0xffffffffu, e == mx);
        int src = __ffs(ball) - 1;                       // lane == local row (lowest-row tie-break)
        int wrow = __shfl_sync(0xffffffffu, myrow, src);
        uint4 csel = a[0];
        #pragma unroll
        for (int r = 1; r < RPW; r++) if (src == r) csel = a[r];
        float winva = __shfl_sync(0xffffffffu, my_inva, src);
        if (mx != 0u) {
            g_wcand[0][gw][lid] = csel;                  // speculative per-warp candidate
            if (lid == 0) g_winfo[0][gw] = make_float2(0.f, winva);
        }
        if (lid == 0) { sh_e[wid] = mx; sh_r[wid] = wrow; }
    }
    __syncthreads();
    if (wid == 0) {
        unsigned e2 = (lid < WPB) ? sh_e[lid] : 0u;
        int      r2 = (lid < WPB) ? sh_r[lid] : 0;
        unsigned mx2 = __reduce_max_sync(0xffffffffu, e2);
        unsigned b2  = __ballot_sync(0xffffffffu, e2 == mx2);
        int src2 = __ffs(b2) - 1;
        int row2 = __shfl_sync(0xffffffffu, r2, src2);
        if (lid == 0) {
            // replay guard: all blocks arrived long ago (during A2) -> ~free
            while (*((volatile unsigned*)&g_bar) < bar_target) { }
            unsigned long long bb = ((unsigned long long)mx2 << 32) | (unsigned)(~row2);
            slot_publish(0, bb, mx2 != 0u);
        }
        cnt_wait(0, (unsigned)nb);
        __threadfence();                                 // acquire
        unsigned long long w = __ldcg(&g_best_a[0][0]);
        // merge softmax partials (published before each block's slot0 arrive)
        float pm = -1e30f, ps = 0.f;
        for (int j = lid; j < nb; j += 32)
            merge_ms(pm, ps, __ldcg(&g_m_part[j]), __ldcg(&g_s_part[j]));
        #pragma unroll
        for (int o = 16; o > 0; o >>= 1) {
            float m2 = __shfl_xor_sync(0xffffffffu, pm, o);
            float s2 = __shfl_xor_sync(0xffffffffu, ps, o);
            merge_ms(pm, ps, m2, s2);
        }
        const int idx0 = (int)(~(unsigned int)w);
        const int gs   = idx0 / RPW;
        sh_v4[lid] = __ldcg(&g_wcand[0][gs][lid]);
        if (lid == 0) {
            sh_bm = pm; sh_bs = ps;
            sh_vinv = __ldcg(&g_winfo[0][gs]).y;
            sh_widx = idx0;
        }
    }
    __syncthreads();
    const float pmax = sh_bm;
    const float invS = 1.0f / sh_bs;
    float myrel = mine ? expf(mypred - pmax) * invS : 0.f;
    float myms  = 0.f;

    // err accumulation on warp1 lane0 (tid 32); err0 from pred directly
    float err_acc = 0.f, decay_t = 1.0f;
    if (bid == 0 && tid == 32)
        err_acc = expf(__ldcg(&pred[sh_widx]) - pmax) * invS;

    // ---------------- greedy loop: 15 passes, all-register GEMV ----------------
    for (int t = 0; t < KSEL - 1; t++) {
        const int   idx  = sh_widx;
        const float vinv = sh_vinv;
        const uint4 vv   = sh_v4[lid];

        float mysim = 0.f;
        #pragma unroll
        for (int i = 0; i < RPW; i++) {
            int d = __dp4a((int)a[i].x, (int)vv.x, 0);
            d = __dp4a((int)a[i].y, (int)vv.y, d);
            d = __dp4a((int)a[i].z, (int)vv.z, d);
            d = __dp4a((int)a[i].w, (int)vv.w, d);
            int ss = (int)__reduce_add_sync(0xffffffffu, (unsigned)d);
            if (lid == i) mysim = (float)ss;
        }
        mysim *= my_inva * vinv;

        const float decay_next = decay_t * DECAYF;
        unsigned e = 0u;
        if (mine) {
            myms = (myrow == idx) ? 1e30f : fmaxf(myms, mysim);
            e = flip_f(decay_next * myrel - LAMBDA * myms);
        }
        unsigned mx = __reduce_max_sync(0xffffffffu, e);
        unsigned ball = __ballot_sync(0xffffffffu, e == mx);
        int src = __ffs(ball) - 1;
        int wrow = __shfl_sync(0xffffffffu, myrow, src);
        uint4 csel = a[0];
        #pragma unroll
        for (int r = 1; r < RPW; r++) if (src == r) csel = a[r];
        float wrel  = __shfl_sync(0xffffffffu, myrel, src);
        float winva = __shfl_sync(0xffffffffu, my_inva, src);
        const int buf = (t + 1) & 1;
        const int k   = t + 1;
        if (mx != 0u) {
            g_wcand[buf][gw][lid] = csel;               // speculative publish before arrive
            if (lid == 0) g_winfo[buf][gw] = make_float2(wrel, winva);
        }
        if (lid == 0) { sh_e[wid] = mx; sh_r[wid] = wrow; }
        __syncthreads();                                 // #1 (orders all warps' STGs before release)

        if (wid == 0) {
            unsigned e2 = (lid < WPB) ? sh_e[lid] : 0u;
            int      r2 = (lid < WPB) ? sh_r[lid] : 0;
            unsigned mx2 = __reduce_max_sync(0xffffffffu, e2);
            unsigned b2  = __ballot_sync(0xffffffffu, e2 == mx2);
            int src2 = __ffs(b2) - 1;
            int row2 = __shfl_sync(0xffffffffu, r2, src2);
            if (lid == 0) {
                unsigned long long bb = ((unsigned long long)mx2 << 32) | (unsigned)(~row2);
                slot_publish(k, bb, mx2 != 0u);
            }
            cnt_wait(k, (unsigned)nb);
            __threadfence();                             // acquire
            unsigned long long w = __ldcg(&g_best_a[k][0]);
            const int nidx = (int)(~(unsigned int)w);
            const int gs   = nidx / RPW;
            if (k < KSEL - 1) {                          // last winner needs no vector
                sh_v4[lid] = __ldcg(&g_wcand[buf][gs][lid]);
                if (lid == 0) sh_vinv = __ldcg(&g_winfo[buf][gs]).y;
            }
            if (lid == 0) sh_widx = nidx;
        }
        __syncthreads();                                 // #2

        decay_t = decay_next;
        if (bid == 0 && tid == 32)
            err_acc += __ldcg(&g_winfo[buf][sh_widx / RPW]).x * decay_t;
    }

    // mmr_loss = -sum over selected of max_j cos = -sum of diagonal = -KSEL (fp32-exact)
    if (bid == 0 && tid == 32)
        out[0] = -err_acc - LAMBDA * (float)KSEL;
}

extern "C" void kernel_launch(void* const* d_in, const int* in_sizes, int n_in,
                              void* d_out, int out_size) {
    (void)in_sizes; (void)n_in; (void)out_size;
    const float* pred = (const float*)d_in[0];
    const float* E    = (const float*)d_in[5];   // explanation_embeddings [32768, 512]
    float* out        = (float*)d_out;

    int dev = 0;
    cudaGetDevice(&dev);
    int nsm = 0;
    cudaDeviceGetAttribute(&nsm, cudaDevAttrMultiProcessorCount, dev);
    if (nsm <= 0) nsm = 148;
    if (nsm > MAXB) nsm = MAXB;

    ranking_kernel<<<nsm, NTHREADS>>>(pred, E, out, nsm);
}

// round 17
// speedup vs baseline: 1.1023x; 1.1023x over previous
#include <cuda_runtime.h>
#include <math.h>

#define NITEMS   32768
#define DIM      512
#define KSEL     16
#define LAMBDA   0.5f
#define DECAYF   0.85f
#define NTHREADS 512
#define WPB      16                     // warps per block
#define RPW      14                     // rows per warp (in registers)
#define RPB      (WPB * RPW)            // 224 rows per block; 148*224 = 33152 >= 32768
#define MAXB     512
#define NGW      (MAXB * WPB)

// ---------------- device scratch (no allocations allowed) ----------------
struct __align__(16) Slot { unsigned long long best; unsigned cnt; unsigned pad; };

__device__ __align__(16) uint4  g_wcand[2][NGW][32];   // per-warp speculative candidate rows (int8)
__device__ __align__(8)  float2 g_winfo[2][NGW];       // (rel, inv_scale) of warp candidate
__device__ float                g_m_part[MAXB];        // online-softmax partial max
__device__ float                g_s_part[MAXB];        // online-softmax partial sum
__device__ Slot                 g_slot[KSEL];          // fused argmax + arrival counter per winner
__device__ unsigned int         g_bar;                 // monotonic barrier (replay-safe reset guard)

// order-preserving float->u32 (monotone increasing); 0 reserved for "invalid"
__device__ __forceinline__ unsigned flip_f(float s) {
    unsigned b = __float_as_uint(s);
    return (b & 0x80000000u) ? ~b : (b | 0x80000000u);
}
__device__ __forceinline__ void merge_ms(float& m, float& s, float m2, float s2) {
    float M = fmaxf(m, m2);
    s = s * expf(m - M) + s2 * expf(m2 - M);
    m = M;
}
// 16B coherent poll: returns final best once cnt == nb (cnt written only after release fence)
__device__ __forceinline__ unsigned long long slot_wait(Slot* sp, unsigned nb) {
    unsigned lo, hi, c, p;
    do {
        asm volatile("ld.volatile.global.v4.u32 {%0,%1,%2,%3}, [%4];"
                     : "=r"(lo), "=r"(hi), "=r"(c), "=r"(p) : "l"(sp));
    } while (c < nb);
    return ((unsigned long long)hi << 32) | lo;
}
// pack 4 s32 -> 4 saturated s8 bytes (2 ops; order consistent across all uses => dp4a-invariant)
__device__ __forceinline__ unsigned pack4_s8(int q0, int q1, int q2, int q3) {
    unsigned t, r, z = 0u;
    asm("cvt.pack.sat.s8.s32.b32 %0, %1, %2, %3;" : "=r"(t) : "r"(q3), "r"(q2), "r"(z));
    asm("cvt.pack.sat.s8.s32.b32 %0, %1, %2, %3;" : "=r"(r) : "r"(q1), "r"(q0), "r"(t));
    return r;
}

__global__ void __launch_bounds__(NTHREADS, 1)
ranking_kernel(const float* __restrict__ pred,
               const float* __restrict__ E,
               float* __restrict__ out,
               int nb)
{
    __shared__ __align__(16) uint4 sh_v4[32];           // staged winner vector, 512 B
    __shared__ unsigned sh_e[WPB];
    __shared__ int      sh_r[WPB];
    __shared__ int      sh_widx;
    __shared__ float    sh_vinv, sh_bm, sh_bs;
    __shared__ float    sh_m[WPB], sh_s[WPB];

    const int tid   = threadIdx.x;
    const int bid   = blockIdx.x;
    const int lid   = tid & 31;
    const int wid   = tid >> 5;
    const int rbase = bid * RPB + wid * RPW;
    const int gw    = bid * WPB + wid;
    const int gthreads = nb * NTHREADS;
    const int gtid     = bid * NTHREADS + tid;

    // reset slots (graph-replay safe); guarded by g_bar before any slot use
    if (bid == 0 && tid == 0) {
        #pragma unroll
        for (int i = 0; i < KSEL; i++) { g_slot[i].best = 0ull; g_slot[i].cnt = 0u; }
    }

    // ---------------- A1: online softmax partials over predictions ----------------
    float m = -1e30f, s = 0.f;
    for (int i = gtid; i < NITEMS; i += gthreads) {
        float p = pred[i];
        float M = fmaxf(m, p);
        s = s * expf(m - M) + expf(p - M);
        m = M;
    }
    #pragma unroll
    for (int o = 16; o > 0; o >>= 1) {
        float m2 = __shfl_xor_sync(0xffffffffu, m, o);
        float s2 = __shfl_xor_sync(0xffffffffu, s, o);
        merge_ms(m, s, m2, s2);
    }
    __syncthreads();
    if (lid == 0) { sh_m[wid] = m; sh_s[wid] = s; }
    __syncthreads();
    if (wid == 0) {
        float pm = (lid < WPB) ? sh_m[lid] : -1e30f;
        float ps = (lid < WPB) ? sh_s[lid] : 0.f;
        #pragma unroll
        for (int o = 16; o > 0; o >>= 1) {
            float m2 = __shfl_xor_sync(0xffffffffu, pm, o);
            float s2 = __shfl_xor_sync(0xffffffffu, ps, o);
            merge_ms(pm, ps, m2, s2);
        }
        if (lid == 0) { g_m_part[bid] = pm; g_s_part[bid] = ps; }
    }

    // arrive the replay-guard barrier (covers slot reset + softmax partials)
    unsigned bar_target = 0u;
    if (tid == 0) {
        __threadfence();
        unsigned tk = atomicAdd(&g_bar, 1u) + 1u;
        bar_target = ((tk + (unsigned)nb - 1u) / (unsigned)nb) * (unsigned)nb;
    }

    // ---------------- A2: quantize-first int8 rows into REGISTERS ----------------
    // inva = 1/sqrt(sum q^2): cos of the QUANTIZED vectors (same int8 error class as before)
    uint4 a[RPW];
    const bool  mine  = (lid < RPW) && (rbase + lid < NITEMS);
    const int   myrow = rbase + lid;
    float my_inva = 0.f, mypred = -1e30f;
    if (mine) mypred = pred[myrow];

    {
        const float4* Erow = reinterpret_cast<const float4*>(E) + (size_t)rbase * (DIM / 4);
        float4 cur[4];
        if (rbase < NITEMS) {
            #pragma unroll
            for (int j = 0; j < 4; j++) cur[j] = Erow[j * 32 + lid];
        }
        #pragma unroll
        for (int i = 0; i < RPW; i++) {
            int row = rbase + i;
            float4 nxt[4];
            bool have_n = (i + 1 < RPW) && (row + 1 < NITEMS);
            if (have_n) {
                const float4* Er2 = Erow + (size_t)(i + 1) * (DIM / 4);
                #pragma unroll
                for (int j = 0; j < 4; j++) nxt[j] = Er2[j * 32 + lid];
            }
            if (row < NITEMS) {
                // max |x| over the raw row (one REDUX; positive floats order as uints)
                float am = 0.f;
                #pragma unroll
                for (int j = 0; j < 4; j++) {
                    am = fmaxf(am, fabsf(cur[j].x)); am = fmaxf(am, fabsf(cur[j].y));
                    am = fmaxf(am, fabsf(cur[j].z)); am = fmaxf(am, fabsf(cur[j].w));
                }
                unsigned amu = __reduce_max_sync(0xffffffffu, __float_as_uint(am));
                float xmax = __uint_as_float(amu);
                const float qs = 127.0f / fmaxf(xmax, 1e-30f);
                int q[16];
                q[0]  = __float2int_rn(cur[0].x * qs); q[1]  = __float2int_rn(cur[0].y * qs);
                q[2]  = __float2int_rn(cur[0].z * qs); q[3]  = __float2int_rn(cur[0].w * qs);
                q[4]  = __float2int_rn(cur[1].x * qs); q[5]  = __float2int_rn(cur[1].y * qs);
                q[6]  = __float2int_rn(cur[1].z * qs); q[7]  = __float2int_rn(cur[1].w * qs);
                q[8]  = __float2int_rn(cur[2].x * qs); q[9]  = __float2int_rn(cur[2].y * qs);
                q[10] = __float2int_rn(cur[2].z * qs); q[11] = __float2int_rn(cur[2].w * qs);
                q[12] = __float2int_rn(cur[3].x * qs); q[13] = __float2int_rn(cur[3].y * qs);
                q[14] = __float2int_rn(cur[3].z * qs); q[15] = __float2int_rn(cur[3].w * qs);
                uint4 u;
                u.x = pack4_s8(q[0],  q[1],  q[2],  q[3]);
                u.y = pack4_s8(q[4],  q[5],  q[6],  q[7]);
                u.z = pack4_s8(q[8],  q[9],  q[10], q[11]);
                u.w = pack4_s8(q[12], q[13], q[14], q[15]);
                a[i] = u;
                // sum q^2 via self-dp4a + one s32 REDUX (exact)
                int d = __dp4a((int)u.x, (int)u.x, 0);
                d = __dp4a((int)u.y, (int)u.y, d);
                d = __dp4a((int)u.z, (int)u.z, d);
                d = __dp4a((int)u.w, (int)u.w, d);
                int sq = (int)__reduce_add_sync(0xffffffffu, (unsigned)d);
                if (lid == i) my_inva = rsqrtf((float)sq);
            } else {
                a[i] = make_uint4(0u, 0u, 0u, 0u);
            }
            #pragma unroll
            for (int j = 0; j < 4; j++) cur[j] = nxt[j];
        }
    }

    // ---------- t=0: argmax(pred) (== argmax(rel), softmax monotone) ----------
    {
        unsigned e = mine ? flip_f(mypred) : 0u;
        unsigned mx = __reduce_max_sync(0xffffffffu, e);
        unsigned ball = __ballot_sync(0xffffffffu, e == mx);
        int src = __ffs(ball) - 1;                       // lane == local row (lowest-row tie-break)
        int wrow = __shfl_sync(0xffffffffu, myrow, src);
        uint4 csel = a[0];
        #pragma unroll
        for (int r = 1; r < RPW; r++) if (src == r) csel = a[r];
        float winva = __shfl_sync(0xffffffffu, my_inva, src);
        if (mx != 0u) {
            g_wcand[0][gw][lid] = csel;                  // speculative per-warp candidate
            if (lid == 0) g_winfo[0][gw] = make_float2(0.f, winva);
        }
        if (lid == 0) { sh_e[wid] = mx; sh_r[wid] = wrow; }
    }
    __syncthreads();
    if (wid == 0) {
        unsigned e2 = (lid < WPB) ? sh_e[lid] : 0u;
        int      r2 = (lid < WPB) ? sh_r[lid] : 0;
        unsigned mx2 = __reduce_max_sync(0xffffffffu, e2);
        unsigned b2  = __ballot_sync(0xffffffffu, e2 == mx2);
        int src2 = __ffs(b2) - 1;
        int row2 = __shfl_sync(0xffffffffu, r2, src2);
        if (lid == 0) {
            // replay guard: all blocks arrived long ago (during A2) -> ~free
            while (*((volatile unsigned*)&g_bar) < bar_target) { }
            if (mx2 != 0u) {
                unsigned long long bb = ((unsigned long long)mx2 << 32) | (unsigned)(~row2);
                atomicMax(&g_slot[0].best, bb);
            }
            __threadfence();                             // release: cand STGs + max
            atomicAdd(&g_slot[0].cnt, 1u);               // arrive
        }
        unsigned long long w = slot_wait(&g_slot[0], (unsigned)nb);
        __threadfence();                                 // acquire
        // merge softmax partials (published before each block's slot0 arrive)
        float pm = -1e30f, ps = 0.f;
        for (int j = lid; j < nb; j += 32)
            merge_ms(pm, ps, __ldcg(&g_m_part[j]), __ldcg(&g_s_part[j]));
        #pragma unroll
        for (int o = 16; o > 0; o >>= 1) {
            float m2 = __shfl_xor_sync(0xffffffffu, pm, o);
            float s2 = __shfl_xor_sync(0xffffffffu, ps, o);
            merge_ms(pm, ps, m2, s2);
        }
        const int idx0 = (int)(~(unsigned int)w);
        const int gs   = idx0 / RPW;
        sh_v4[lid] = __ldcg(&g_wcand[0][gs][lid]);
        if (lid == 0) {
            sh_bm = pm; sh_bs = ps;
            sh_vinv = __ldcg(&g_winfo[0][gs]).y;
            sh_widx = idx0;
        }
    }
    __syncthreads();
    const float pmax = sh_bm;
    const float invS = 1.0f / sh_bs;
    float myrel = mine ? expf(mypred - pmax) * invS : 0.f;
    float myms  = 0.f;

    // err accumulation on warp1 lane0 (tid 32); err0 from pred directly
    float err_acc = 0.f, decay_t = 1.0f;
    if (bid == 0 && tid == 32)
        err_acc = expf(__ldcg(&pred[sh_widx]) - pmax) * invS;

    // ---------------- greedy loop: 15 passes, all-register GEMV ----------------
    for (int t = 0; t < KSEL - 1; t++) {
        const int   idx  = sh_widx;
        const float vinv = sh_vinv;
        const uint4 vv   = sh_v4[lid];

        float mysim = 0.f;
        #pragma unroll
        for (int i = 0; i < RPW; i++) {
            int d = __dp4a((int)a[i].x, (int)vv.x, 0);
            d = __dp4a((int)a[i].y, (int)vv.y, d);
            d = __dp4a((int)a[i].z, (int)vv.z, d);
            d = __dp4a((int)a[i].w, (int)vv.w, d);
            int ss = (int)__reduce_add_sync(0xffffffffu, (unsigned)d);
            if (lid == i) mysim = (float)ss;
        }
        mysim *= my_inva * vinv;

        const float decay_next = decay_t * DECAYF;
        unsigned e = 0u;
        if (mine) {
            myms = (myrow == idx) ? 1e30f : fmaxf(myms, mysim);
            e = flip_f(decay_next * myrel - LAMBDA * myms);
        }
        unsigned mx = __reduce_max_sync(0xffffffffu, e);
        unsigned ball = __ballot_sync(0xffffffffu, e == mx);
        int src = __ffs(ball) - 1;
        int wrow = __shfl_sync(0xffffffffu, myrow, src);
        uint4 csel = a[0];
        #pragma unroll
        for (int r = 1; r < RPW; r++) if (src == r) csel = a[r];
        float wrel  = __shfl_sync(0xffffffffu, myrel, src);
        float winva = __shfl_sync(0xffffffffu, my_inva, src);
        const int buf = (t + 1) & 1;
        const int k   = t + 1;
        if (mx != 0u) {
            g_wcand[buf][gw][lid] = csel;               // speculative publish before arrive
            if (lid == 0) g_winfo[buf][gw] = make_float2(wrel, winva);
        }
        if (lid == 0) { sh_e[wid] = mx; sh_r[wid] = wrow; }
        __syncthreads();                                 // #1 (orders all warps' STGs before release)

        if (wid == 0) {
            unsigned e2 = (lid < WPB) ? sh_e[lid] : 0u;
            int      r2 = (lid < WPB) ? sh_r[lid] : 0;
            unsigned mx2 = __reduce_max_sync(0xffffffffu, e2);
            unsigned b2  = __ballot_sync(0xffffffffu, e2 == mx2);
            int src2 = __ffs(b2) - 1;
            int row2 = __shfl_sync(0xffffffffu, r2, src2);
            if (lid == 0) {
                if (mx2 != 0u) {
                    unsigned long long bb = ((unsigned long long)mx2 << 32) | (unsigned)(~row2);
                    atomicMax(&g_slot[k].best, bb);
                }
                __threadfence();
                atomicAdd(&g_slot[k].cnt, 1u);
            }
            unsigned long long w = slot_wait(&g_slot[k], (unsigned)nb);
            __threadfence();                             // acquire
            const int nidx = (int)(~(unsigned int)w);
            const int gs   = nidx / RPW;
            if (k < KSEL - 1) {                          // last winner needs no vector
                sh_v4[lid] = __ldcg(&g_wcand[buf][gs][lid]);
                if (lid == 0) sh_vinv = __ldcg(&g_winfo[buf][gs]).y;
            }
            if (lid == 0) sh_widx = nidx;
        }
        __syncthreads();                                 // #2

        decay_t = decay_next;
        if (bid == 0 && tid == 32)
            err_acc += __ldcg(&g_winfo[buf][sh_widx / RPW]).x * decay_t;
    }

    // mmr_loss = -sum over selected of max_j cos = -sum of diagonal = -KSEL (fp32-exact)
    if (bid == 0 && tid == 32)
        out[0] = -err_acc - LAMBDA * (float)KSEL;
}

extern "C" void kernel_launch(void* const* d_in, const int* in_sizes, int n_in,
                              void* d_out, int out_size) {
    (void)in_sizes; (void)n_in; (void)out_size;
    const float* pred = (const float*)d_in[0];
    const float* E    = (const float*)d_in[5];   // explanation_embeddings [32768, 512]
    float* out        = (float*)d_out;

    int dev = 0;
    cudaGetDevice(&dev);
    int nsm = 0;
    cudaDeviceGetAttribute(&nsm, cudaDevAttrMultiProcessorCount, dev);
    if (nsm <= 0) nsm = 148;
    if (nsm > MAXB) nsm = MAXB;

    ranking_kernel<<<nsm, NTHREADS>>>(pred, E, out, nsm);
}